// round 2
// baseline (speedup 1.0000x reference)
#include <cuda_runtime.h>
#include <cuda_fp16.h>
#include <cstdint>

// Problem: out[b,s,o] = f32( f16( fp32(x) @ (int8 W * group_scale) ) + f16 bias )
//   M = 8192, N = 11008, K = 4096, GROUP = 128
// Harness dtypes (inferred): x f32 [M,K], weight i32 (or i8 - probed) [N,K],
//   scale f32 [N,K/128], bias f32 [N], out f32 [M,N]

#define M_TOTAL 8192
#define N_TOTAL 11008
#define K_TOTAL 4096
#define GROUPSZ 128

#define BM 128
#define BN 128
#define BK 32
#define LDS_A 40   // 32 + 8 pad halves; 80B row stride -> conflict-free ldmatrix
#define LDS_B 40

// ---------------- dtype probe: is the weight buffer int32 or int8? ----------
__device__ int g_w_is_i32;

__global__ void probe_weight_kernel(const int8_t* __restrict__ w)
{
    if (threadIdx.x != 0 || blockIdx.x != 0) return;
    int votes = 0;
#pragma unroll
    for (int i = 0; i < 16; i++) {
        int8_t b0 = w[i * 4 + 0];
        int8_t b1 = w[i * 4 + 1];
        int8_t b2 = w[i * 4 + 2];
        int8_t b3 = w[i * 4 + 3];
        int8_t ext = (b0 < 0) ? (int8_t)-1 : (int8_t)0;
        if (b1 == ext && b2 == ext && b3 == ext) votes++;
    }
    g_w_is_i32 = (votes >= 14) ? 1 : 0;
}

// ---------------- main GEMM ----------------
template <bool WI32>
__global__ __launch_bounds__(256) void wq8_gemm_kernel(
    const float* __restrict__ X,
    const void*  __restrict__ Wv,
    const float* __restrict__ S,
    const float* __restrict__ BIAS,
    float* __restrict__ O)
{
    if ((g_w_is_i32 != 0) != WI32) return;

    __shared__ __align__(16) __half As[2][BM][LDS_A];
    __shared__ __align__(16) __half Bs[2][BN][LDS_B];

    const int tid  = threadIdx.x;
    const int lane = tid & 31;
    const int warp = tid >> 5;
    const int wm   = warp >> 2;   // 0..1 : 64-row slab
    const int wn   = warp & 3;    // 0..3 : 32-col slab

    const int m0 = blockIdx.y * BM;
    const int n0 = blockIdx.x * BN;

    float acc[4][4][4];
#pragma unroll
    for (int i = 0; i < 4; i++)
#pragma unroll
        for (int j = 0; j < 4; j++)
#pragma unroll
            for (int k = 0; k < 4; k++) acc[i][j][k] = 0.f;

    // ---- staging registers ----
    uint4 a_st[4];               // A tile: 128x32 f32 = 1024 uint4; 4/thread
    uint4 w_st[WI32 ? 4 : 1];    // W tile: i32 -> 1024 uint4 (4/thr); i8 -> 256 (1/thr)
    float s_st[WI32 ? 4 : 1];

    auto load_g = [&](int kb) {
#pragma unroll
        for (int i = 0; i < 4; i++) {
            int id  = tid + i * 256;
            int row = id >> 3;          // 8 uint4 per 32-float row
            int c4  = (id & 7) * 4;
            a_st[i] = *reinterpret_cast<const uint4*>(
                X + (size_t)(m0 + row) * K_TOTAL + kb + c4);
        }
        if (WI32) {
            const int* W = (const int*)Wv;
#pragma unroll
            for (int i = 0; i < 4; i++) {
                int id  = tid + i * 256;
                int row = id >> 3;
                int c4  = (id & 7) * 4;
                w_st[i] = *reinterpret_cast<const uint4*>(
                    W + (size_t)(n0 + row) * K_TOTAL + kb + c4);
                s_st[i] = S[(size_t)(n0 + row) * (K_TOTAL / GROUPSZ) + (kb >> 7)];
            }
        } else {
            const int8_t* W = (const int8_t*)Wv;
            int row = tid >> 1;          // 2 x 16B per 32-byte row
            int col = (tid & 1) * 16;
            w_st[0] = *reinterpret_cast<const uint4*>(
                W + (size_t)(n0 + row) * K_TOTAL + kb + col);
            s_st[0] = S[(size_t)(n0 + row) * (K_TOTAL / GROUPSZ) + (kb >> 7)];
        }
    };

    auto store_s = [&](int buf) {
#pragma unroll
        for (int i = 0; i < 4; i++) {
            int id  = tid + i * 256;
            int row = id >> 3;
            int c4  = (id & 7) * 4;
            const float* f = reinterpret_cast<const float*>(&a_st[i]);
            __half2 h0 = __floats2half2_rn(f[0], f[1]);
            __half2 h1 = __floats2half2_rn(f[2], f[3]);
            uint2 pk = make_uint2(*(const uint32_t*)&h0, *(const uint32_t*)&h1);
            *reinterpret_cast<uint2*>(&As[buf][row][c4]) = pk;
        }
        if (WI32) {
#pragma unroll
            for (int i = 0; i < 4; i++) {
                int id  = tid + i * 256;
                int row = id >> 3;
                int c4  = (id & 7) * 4;
                const int* v = reinterpret_cast<const int*>(&w_st[i]);
                float sc = s_st[i];
                __half2 h0 = __floats2half2_rn((float)v[0] * sc, (float)v[1] * sc);
                __half2 h1 = __floats2half2_rn((float)v[2] * sc, (float)v[3] * sc);
                uint2 pk = make_uint2(*(const uint32_t*)&h0, *(const uint32_t*)&h1);
                *reinterpret_cast<uint2*>(&Bs[buf][row][c4]) = pk;
            }
        } else {
            int row = tid >> 1;
            int col = (tid & 1) * 16;
            const int8_t* wb = reinterpret_cast<const int8_t*>(&w_st[0]);
            float sc = s_st[0];
            __half hv[16];
#pragma unroll
            for (int j = 0; j < 16; j++)
                hv[j] = __float2half((float)wb[j] * sc);
            *reinterpret_cast<uint4*>(&Bs[buf][row][col])     = *reinterpret_cast<uint4*>(&hv[0]);
            *reinterpret_cast<uint4*>(&Bs[buf][row][col + 8]) = *reinterpret_cast<uint4*>(&hv[8]);
        }
    };

    auto compute = [&](int buf) {
#pragma unroll
        for (int ks = 0; ks < 2; ks++) {
            uint32_t af[4][4];
#pragma unroll
            for (int mi = 0; mi < 4; mi++) {
                const __half* p =
                    &As[buf][wm * 64 + mi * 16 + (lane & 15)][ks * 16 + (lane >> 4) * 8];
                uint32_t addr = (uint32_t)__cvta_generic_to_shared(p);
                asm volatile(
                    "ldmatrix.sync.aligned.m8n8.x4.shared.b16 {%0,%1,%2,%3}, [%4];"
                    : "=r"(af[mi][0]), "=r"(af[mi][1]), "=r"(af[mi][2]), "=r"(af[mi][3])
                    : "r"(addr));
            }
            uint32_t bf[8];
#pragma unroll
            for (int bi = 0; bi < 2; bi++) {
                int mm = lane >> 3;
                int nr = wn * 32 + bi * 16 + ((mm >> 1) << 3) + (lane & 7);
                int kk = ks * 16 + ((mm & 1) << 3);
                const __half* p = &Bs[buf][nr][kk];
                uint32_t addr = (uint32_t)__cvta_generic_to_shared(p);
                asm volatile(
                    "ldmatrix.sync.aligned.m8n8.x4.shared.b16 {%0,%1,%2,%3}, [%4];"
                    : "=r"(bf[bi * 4]), "=r"(bf[bi * 4 + 1]),
                      "=r"(bf[bi * 4 + 2]), "=r"(bf[bi * 4 + 3])
                    : "r"(addr));
            }
#pragma unroll
            for (int mi = 0; mi < 4; mi++)
#pragma unroll
                for (int ni = 0; ni < 4; ni++) {
                    asm volatile(
                        "mma.sync.aligned.m16n8k16.row.col.f32.f16.f16.f32 "
                        "{%0,%1,%2,%3}, {%4,%5,%6,%7}, {%8,%9}, {%0,%1,%2,%3};"
                        : "+f"(acc[mi][ni][0]), "+f"(acc[mi][ni][1]),
                          "+f"(acc[mi][ni][2]), "+f"(acc[mi][ni][3])
                        : "r"(af[mi][0]), "r"(af[mi][1]), "r"(af[mi][2]), "r"(af[mi][3]),
                          "r"(bf[ni * 2]), "r"(bf[ni * 2 + 1]));
                }
        }
    };

    // ---- mainloop: double-buffered smem, register-staged global loads ----
    load_g(0);
    store_s(0);
    __syncthreads();

    int buf = 0;
    const int NT = K_TOTAL / BK;  // 128
    for (int t = 0; t < NT; t++) {
        if (t + 1 < NT) load_g((t + 1) * BK);
        compute(buf);
        if (t + 1 < NT) {
            store_s(buf ^ 1);
            __syncthreads();
            buf ^= 1;
        }
    }

    // ---- epilogue: replicate reference rounding: f16(acc) + f16(bias), store f32 ----
#pragma unroll
    for (int mi = 0; mi < 4; mi++) {
#pragma unroll
        for (int ni = 0; ni < 4; ni++) {
            int col = n0 + wn * 32 + ni * 8 + (lane & 3) * 2;
            float2 bf2 = *reinterpret_cast<const float2*>(BIAS + col);
            __half2 b2 = __floats2half2_rn(bf2.x, bf2.y);
            int r0 = m0 + wm * 64 + mi * 16 + (lane >> 2);

            __half2 v0 = __floats2half2_rn(acc[mi][ni][0], acc[mi][ni][1]);
            __half2 v1 = __floats2half2_rn(acc[mi][ni][2], acc[mi][ni][3]);
            __half2 r0h = __hadd2(v0, b2);
            __half2 r1h = __hadd2(v1, b2);
            float2 o0 = __half22float2(r0h);
            float2 o1 = __half22float2(r1h);
            *reinterpret_cast<float2*>(O + (size_t)r0 * N_TOTAL + col) = o0;
            *reinterpret_cast<float2*>(O + (size_t)(r0 + 8) * N_TOTAL + col) = o1;
        }
    }
}

extern "C" void kernel_launch(void* const* d_in, const int* in_sizes, int n_in,
                              void* d_out, int out_size)
{
    const float* x    = (const float*)d_in[0];
    const void*  w    = (const void*)d_in[1];
    const float* s    = (const float*)d_in[2];
    const float* bias = (const float*)d_in[3];
    float*       out  = (float*)d_out;

    probe_weight_kernel<<<1, 32>>>((const int8_t*)w);

    dim3 grid(N_TOTAL / BN, M_TOTAL / BM);  // 86 x 64
    wq8_gemm_kernel<true ><<<grid, 256>>>(x, w, s, bias, out);
    wq8_gemm_kernel<false><<<grid, 256>>>(x, w, s, bias, out);
}

// round 4
// speedup vs baseline: 1.5056x; 1.5056x over previous
#include <cuda_runtime.h>
#include <cuda_fp16.h>
#include <cstdint>

// out[m,n] = f32( f16( f32x[m,:] . (W[n,:]*scale) ) + f16(bias[n]) )
// Harness dtypes: x f32 [M,K], weight i32-or-i8 (probed) [N,K],
// scale f32 [N,K/128], bias f32 [N], out f32 [M,N]
// compute_103 virtual arch: NO tcgen05. Ceiling = legacy HMMA (mma.sync).

#define M_TOTAL 8192
#define N_TOTAL 11008
#define K_TOTAL 4096
#define GROUPSZ 128

#define BM 128
#define BN 128
#define BK 64
#define NSTAGE 3
#define NT (K_TOTAL / BK)   // 64
#define LDS_A 72            // 64 + 8 pad halves; 144B stride -> +4 banks/row, conflict-free
#define LDS_B 72

#define SMEM_BYTES (NSTAGE * (BM * LDS_A + BN * LDS_B) * 2)  // 110592

// ---------------- scratch (f16 prepass outputs) ----------------
__device__ __half g_Ah[(size_t)M_TOTAL * K_TOTAL];   // 64 MB
__device__ __half g_Bh[(size_t)N_TOTAL * K_TOTAL];   // 88 MB
__device__ int    g_w_is_i32;

__device__ __forceinline__ uint32_t smem_u32(const void* p) {
    uint32_t a;
    asm("{ .reg .u64 t; cvta.to.shared.u64 t, %1; cvt.u32.u64 %0, t; }"
        : "=r"(a) : "l"(p));
    return a;
}

#define CP_ASYNC_16(dst_u32, src_ptr) \
    asm volatile("cp.async.cg.shared.global [%0], [%1], 16;" \
                 :: "r"(dst_u32), "l"(src_ptr) : "memory")
#define CP_COMMIT() asm volatile("cp.async.commit_group;" ::: "memory")
#define CP_WAIT(n)  asm volatile("cp.async.wait_group %0;" :: "n"(n) : "memory")

// ---------------- dtype probe ----------------
__global__ void probe_weight_kernel(const int8_t* __restrict__ w)
{
    if (threadIdx.x != 0 || blockIdx.x != 0) return;
    int votes = 0;
#pragma unroll
    for (int i = 0; i < 16; i++) {
        int8_t b0 = w[i * 4 + 0], b1 = w[i * 4 + 1], b2 = w[i * 4 + 2], b3 = w[i * 4 + 3];
        int8_t ext = (b0 < 0) ? (int8_t)-1 : (int8_t)0;
        if (b1 == ext && b2 == ext && b3 == ext) votes++;
    }
    g_w_is_i32 = (votes >= 14) ? 1 : 0;
}

// ---------------- prepass: x f32 -> f16 ----------------
__global__ __launch_bounds__(256) void convert_x_kernel(const float4* __restrict__ X)
{
    size_t i = (size_t)blockIdx.x * 256 + threadIdx.x;  // 8 floats / thread
    float4 a = X[2 * i], b = X[2 * i + 1];
    __half2 h0 = __floats2half2_rn(a.x, a.y);
    __half2 h1 = __floats2half2_rn(a.z, a.w);
    __half2 h2 = __floats2half2_rn(b.x, b.y);
    __half2 h3 = __floats2half2_rn(b.z, b.w);
    uint4 pk;
    pk.x = *(const uint32_t*)&h0; pk.y = *(const uint32_t*)&h1;
    pk.z = *(const uint32_t*)&h2; pk.w = *(const uint32_t*)&h3;
    reinterpret_cast<uint4*>(g_Ah)[i] = pk;
}

// ---------------- prepass: W dequant -> f16 ----------------
__global__ __launch_bounds__(256) void dequant_w_kernel(const void* __restrict__ Wv,
                                                        const float* __restrict__ S)
{
    size_t i = (size_t)blockIdx.x * 256 + threadIdx.x;  // 8 weights / thread
    size_t base = i * 8;
    int n = (int)(base / K_TOTAL);
    int k = (int)(base % K_TOTAL);
    float sc = S[(size_t)n * (K_TOTAL / GROUPSZ) + (k >> 7)];

    float f[8];
    if (g_w_is_i32) {
        const int4* W = reinterpret_cast<const int4*>(Wv);
        int4 v0 = W[i * 2], v1 = W[i * 2 + 1];
        f[0] = (float)v0.x; f[1] = (float)v0.y; f[2] = (float)v0.z; f[3] = (float)v0.w;
        f[4] = (float)v1.x; f[5] = (float)v1.y; f[6] = (float)v1.z; f[7] = (float)v1.w;
    } else {
        uint2 raw = reinterpret_cast<const uint2*>(Wv)[i];
        const int8_t* b = reinterpret_cast<const int8_t*>(&raw);
#pragma unroll
        for (int j = 0; j < 8; j++) f[j] = (float)b[j];
    }
    __half2 h0 = __floats2half2_rn(f[0] * sc, f[1] * sc);
    __half2 h1 = __floats2half2_rn(f[2] * sc, f[3] * sc);
    __half2 h2 = __floats2half2_rn(f[4] * sc, f[5] * sc);
    __half2 h3 = __floats2half2_rn(f[6] * sc, f[7] * sc);
    uint4 pk;
    pk.x = *(const uint32_t*)&h0; pk.y = *(const uint32_t*)&h1;
    pk.z = *(const uint32_t*)&h2; pk.w = *(const uint32_t*)&h3;
    reinterpret_cast<uint4*>(g_Bh)[i] = pk;
}

// ---------------- HMMA GEMM with cp.async 3-stage pipeline ----------------
__global__ __launch_bounds__(256, 2) void wq8_gemm_kernel(
    const float* __restrict__ BIAS,
    float* __restrict__ O)
{
    extern __shared__ __align__(16) __half smem[];
    __half (*As)[BM][LDS_A] = reinterpret_cast<__half (*)[BM][LDS_A]>(smem);
    __half (*Bs)[BN][LDS_B] =
        reinterpret_cast<__half (*)[BN][LDS_B]>(smem + NSTAGE * BM * LDS_A);

    const int tid  = threadIdx.x;
    const int lane = tid & 31;
    const int warp = tid >> 5;
    const int wm   = warp >> 2;   // 0..1 : 64-row slab
    const int wn   = warp & 3;    // 0..3 : 32-col slab

    const int m0 = blockIdx.y * BM;
    const int n0 = blockIdx.x * BN;

    float acc[4][4][4];
#pragma unroll
    for (int i = 0; i < 4; i++)
#pragma unroll
        for (int j = 0; j < 4; j++)
#pragma unroll
            for (int k = 0; k < 4; k++) acc[i][j][k] = 0.f;

    // per-thread load plan: tile 128 rows x 64 halves = 8 x 16B chunks/row
    // = 1024 chunks; 256 threads -> 4 chunks each (A and B alike)
    const int l_row = tid >> 3;          // base row 0..31 (+32*i)
    const int l_col = (tid & 7) * 8;     // half offset

    auto issue_stage = [&](int s, int kb) {
#pragma unroll
        for (int i = 0; i < 4; i++) {
            int row = l_row + i * 32;
            uint32_t d = smem_u32(&As[s][row][l_col]);
            CP_ASYNC_16(d, g_Ah + (size_t)(m0 + row) * K_TOTAL + kb + l_col);
        }
#pragma unroll
        for (int i = 0; i < 4; i++) {
            int row = l_row + i * 32;
            uint32_t d = smem_u32(&Bs[s][row][l_col]);
            CP_ASYNC_16(d, g_Bh + (size_t)(n0 + row) * K_TOTAL + kb + l_col);
        }
    };

    auto compute = [&](int s) {
#pragma unroll
        for (int ks = 0; ks < 4; ks++) {
            uint32_t af[4][4];
#pragma unroll
            for (int mi = 0; mi < 4; mi++) {
                const __half* p =
                    &As[s][wm * 64 + mi * 16 + (lane & 15)][ks * 16 + (lane >> 4) * 8];
                uint32_t addr = smem_u32(p);
                asm volatile(
                    "ldmatrix.sync.aligned.m8n8.x4.shared.b16 {%0,%1,%2,%3}, [%4];"
                    : "=r"(af[mi][0]), "=r"(af[mi][1]), "=r"(af[mi][2]), "=r"(af[mi][3])
                    : "r"(addr));
            }
            uint32_t bf[8];
#pragma unroll
            for (int bi = 0; bi < 2; bi++) {
                int mm = lane >> 3;
                int nr = wn * 32 + bi * 16 + ((mm >> 1) << 3) + (lane & 7);
                int kk = ks * 16 + ((mm & 1) << 3);
                uint32_t addr = smem_u32(&Bs[s][nr][kk]);
                asm volatile(
                    "ldmatrix.sync.aligned.m8n8.x4.shared.b16 {%0,%1,%2,%3}, [%4];"
                    : "=r"(bf[bi * 4]), "=r"(bf[bi * 4 + 1]),
                      "=r"(bf[bi * 4 + 2]), "=r"(bf[bi * 4 + 3])
                    : "r"(addr));
            }
#pragma unroll
            for (int mi = 0; mi < 4; mi++)
#pragma unroll
                for (int ni = 0; ni < 4; ni++) {
                    asm volatile(
                        "mma.sync.aligned.m16n8k16.row.col.f32.f16.f16.f32 "
                        "{%0,%1,%2,%3}, {%4,%5,%6,%7}, {%8,%9}, {%0,%1,%2,%3};"
                        : "+f"(acc[mi][ni][0]), "+f"(acc[mi][ni][1]),
                          "+f"(acc[mi][ni][2]), "+f"(acc[mi][ni][3])
                        : "r"(af[mi][0]), "r"(af[mi][1]), "r"(af[mi][2]), "r"(af[mi][3]),
                          "r"(bf[ni * 2]), "r"(bf[ni * 2 + 1]));
                }
        }
    };

    // prologue: fill all 3 stages
#pragma unroll
    for (int s = 0; s < NSTAGE; s++) {
        issue_stage(s, s * BK);
        CP_COMMIT();
    }

    for (int t = 0; t < NT; t++) {
        CP_WAIT(NSTAGE - 1);     // stage t complete (invariant: always 3 pending)
        __syncthreads();
        compute(t % NSTAGE);
        __syncthreads();         // all warps done reading stage t before refill
        if (t + NSTAGE < NT) issue_stage(t % NSTAGE, (t + NSTAGE) * BK);
        CP_COMMIT();             // empty group in tail keeps wait-count invariant
    }

    // ---- epilogue: f16(acc) + f16(bias), store f32 (matches reference rounding) ----
#pragma unroll
    for (int mi = 0; mi < 4; mi++) {
#pragma unroll
        for (int ni = 0; ni < 4; ni++) {
            int col = n0 + wn * 32 + ni * 8 + (lane & 3) * 2;
            float2 bf2 = *reinterpret_cast<const float2*>(BIAS + col);
            __half2 b2 = __floats2half2_rn(bf2.x, bf2.y);
            int r0 = m0 + wm * 64 + mi * 16 + (lane >> 2);

            __half2 v0 = __floats2half2_rn(acc[mi][ni][0], acc[mi][ni][1]);
            __half2 v1 = __floats2half2_rn(acc[mi][ni][2], acc[mi][ni][3]);
            float2 o0 = __half22float2(__hadd2(v0, b2));
            float2 o1 = __half22float2(__hadd2(v1, b2));
            *reinterpret_cast<float2*>(O + (size_t)r0 * N_TOTAL + col) = o0;
            *reinterpret_cast<float2*>(O + (size_t)(r0 + 8) * N_TOTAL + col) = o1;
        }
    }
}

extern "C" void kernel_launch(void* const* d_in, const int* in_sizes, int n_in,
                              void* d_out, int out_size)
{
    const float* x    = (const float*)d_in[0];
    const void*  w    = (const void*)d_in[1];
    const float* s    = (const float*)d_in[2];
    const float* bias = (const float*)d_in[3];
    float*       out  = (float*)d_out;

    cudaFuncSetAttribute(wq8_gemm_kernel,
                         cudaFuncAttributeMaxDynamicSharedMemorySize, SMEM_BYTES);

    probe_weight_kernel<<<1, 32>>>((const int8_t*)w);
    convert_x_kernel<<<(int)((size_t)M_TOTAL * K_TOTAL / 8 / 256), 256>>>(
        (const float4*)x);
    dequant_w_kernel<<<(int)((size_t)N_TOTAL * K_TOTAL / 8 / 256), 256>>>(w, s);

    dim3 grid(N_TOTAL / BN, M_TOTAL / BM);  // 86 x 64
    wq8_gemm_kernel<<<grid, 256, SMEM_BYTES>>>(bias, out);
}